// round 4
// baseline (speedup 1.0000x reference)
#include <cuda_runtime.h>
#include <cuda_bf16.h>
#include <math.h>

#define N_NODES 100000
#define N_EDGES 1600000
#define IN_DIM  512
#define HID     64
#define OUTD    32

// ---------------- scratch (static device globals; no allocation) ----------------
__device__ int   g_deg[N_NODES];
__device__ float g_dinv[N_NODES];
__device__ int   g_off[N_NODES + 1];
__device__ int   g_cur[N_NODES];
__device__ int   g_srcs[N_EDGES];
__device__ float g_wgt[N_EDGES];
__device__ float g_h1[(size_t)N_NODES * HID];   // 25.6 MB
__device__ float g_h2[(size_t)N_NODES * OUTD];  // 12.8 MB
__device__ int   g_bsum[256];
__device__ int   g_is64;

// ---------------- edge-index dtype detection (int64 vs int32) ----------------
__global__ void k_detect(const long long* __restrict__ ei) {
    __shared__ int ok;
    if (threadIdx.x == 0) ok = 1;
    __syncthreads();
    for (int j = threadIdx.x; j < 2048; j += blockDim.x) {
        long long v = ei[j];
        if (v < 0 || v >= N_NODES) atomicExch(&ok, 0);
    }
    __syncthreads();
    if (threadIdx.x == 0) g_is64 = ok;
}

__device__ __forceinline__ int load_edge(const void* ei, int part, int e) {
    if (g_is64) return (int)((const long long*)ei)[(size_t)part * N_EDGES + e];
    return ((const int*)ei)[(size_t)part * N_EDGES + e];
}

// ---------------- degree / hist ----------------
__global__ void k_init() {
    int v = blockIdx.x * blockDim.x + threadIdx.x;
    if (v < N_NODES) g_deg[v] = 1;  // self-loop
}

__global__ void k_hist(const void* __restrict__ ei) {
    int e = blockIdx.x * blockDim.x + threadIdx.x;
    if (e < N_EDGES) atomicAdd(&g_deg[load_edge(ei, 1, e)], 1);
}

// ---------------- exclusive scan of (deg-1) to build CSR offsets ----------------
__global__ void k_scan1() {
    __shared__ int s[512];
    int t = threadIdx.x;
    int v = blockIdx.x * 512 + t;
    int c = (v < N_NODES) ? (g_deg[v] - 1) : 0;
    s[t] = c;
    __syncthreads();
    for (int o = 1; o < 512; o <<= 1) {
        int val = (t >= o) ? s[t - o] : 0;
        __syncthreads();
        s[t] += val;
        __syncthreads();
    }
    if (v < N_NODES) g_off[v] = s[t] - c;
    if (t == 511) g_bsum[blockIdx.x] = s[511];
}

__global__ void k_scan2(int nb) {
    __shared__ int s[256];
    int t = threadIdx.x;
    int c = (t < nb) ? g_bsum[t] : 0;
    s[t] = c;
    __syncthreads();
    for (int o = 1; o < 256; o <<= 1) {
        int val = (t >= o) ? s[t - o] : 0;
        __syncthreads();
        s[t] += val;
        __syncthreads();
    }
    if (t < nb) g_bsum[t] = s[t] - c;
}

__global__ void k_scan3() {  // finalize offsets + compute dinv
    int v = blockIdx.x * blockDim.x + threadIdx.x;
    if (v < N_NODES) {
        int o = g_off[v] + g_bsum[v >> 9];
        g_off[v] = o;
        g_cur[v] = o;
        g_dinv[v] = rsqrtf((float)g_deg[v]);
    }
    if (v == 0) g_off[N_NODES] = N_EDGES;
}

__global__ void k_scatter(const void* __restrict__ ei) {
    int e = blockIdx.x * blockDim.x + threadIdx.x;
    if (e < N_EDGES) {
        int d = load_edge(ei, 1, e);
        int s = load_edge(ei, 0, e);
        int pos = atomicAdd(&g_cur[d], 1);
        g_srcs[pos] = s;
        g_wgt[pos] = g_dinv[s] * g_dinv[d];
    }
}

// ---------------- GEMM1: h1 = x @ W1 via bf16 mma, A fragments direct from gmem ----
// 128 threads (4 warps) per CTA, each warp owns 32 rows. W1 split hi/lo per
// 64-k chunk into smem fragment layout (stride 36 words, conflict-free).
#define BMG   128
#define BSTRH 72   // halves per B row (64 + 8 pad); 36 words

__device__ __forceinline__ void mma16816(float* c, const unsigned* a, const unsigned* b) {
    asm volatile(
        "mma.sync.aligned.m16n8k16.row.col.f32.bf16.bf16.f32 "
        "{%0,%1,%2,%3}, {%4,%5,%6,%7}, {%8,%9}, {%0,%1,%2,%3};\n"
        : "+f"(c[0]), "+f"(c[1]), "+f"(c[2]), "+f"(c[3])
        : "r"(a[0]), "r"(a[1]), "r"(a[2]), "r"(a[3]), "r"(b[0]), "r"(b[1]));
}

__device__ __forceinline__ unsigned pack_hi(float2 v, __nv_bfloat162* h2out) {
    __nv_bfloat162 h2 = __float22bfloat162_rn(v);  // .x -> low half
    *h2out = h2;
    return *(unsigned*)&h2;
}
__device__ __forceinline__ unsigned pack_lo(float2 v, __nv_bfloat162 h2) {
    float2 l;
    l.x = v.x - __bfloat162float(h2.x);
    l.y = v.y - __bfloat162float(h2.y);
    __nv_bfloat162 l2 = __float22bfloat162_rn(l);
    return *(unsigned*)&l2;
}

__global__ __launch_bounds__(128, 4) void k_gemm1(const float* __restrict__ x,
                                                  const float* __restrict__ W1) {
    __shared__ __nv_bfloat16 Bh[64 * BSTRH];
    __shared__ __nv_bfloat16 Bl[64 * BSTRH];

    const int t = threadIdx.x;
    const int warp = t >> 5, lane = t & 31;
    const int q = lane & 3, lr = lane >> 2;
    const int rbase = blockIdx.x * BMG + warp * 32;

    // 4 row slots: rbase + lr + {0,8,16,24}
    bool vld[4];
    const float* xp[4];
#pragma unroll
    for (int i = 0; i < 4; i++) {
        int r = rbase + lr + i * 8;
        vld[i] = r < N_NODES;
        xp[i] = x + (size_t)(vld[i] ? r : 0) * IN_DIM;
    }

    float acc[2][8][4];
#pragma unroll
    for (int m = 0; m < 2; m++)
#pragma unroll
        for (int n = 0; n < 8; n++)
#pragma unroll
            for (int j = 0; j < 4; j++) acc[m][n][j] = 0.f;

    float2 vc[8], vn[8];
    const int c0 = 2 * q;  // within-kstep col offsets: c0 and c0+8

    // initial A prefetch (kstep 0)
#pragma unroll
    for (int i = 0; i < 4; i++) {
        vc[2 * i]     = vld[i] ? __ldcs((const float2*)(xp[i] + c0))     : make_float2(0.f, 0.f);
        vc[2 * i + 1] = vld[i] ? __ldcs((const float2*)(xp[i] + c0 + 8)) : make_float2(0.f, 0.f);
    }

    for (int kt = 0; kt < IN_DIM; kt += 64) {
        __syncthreads();  // previous chunk's mma reads done
        // ---- convert W1 chunk [kt..kt+64) x 64 into Bh/Bl fragment layout
#pragma unroll
        for (int i = 0; i < 8; i++) {
            int f4 = t + 128 * i;            // 0..1023
            int k = f4 >> 4, cc = f4 & 15;
            float4 v = *(const float4*)(W1 + (size_t)(kt + k) * 64 + cc * 4);
            float vv[4] = {v.x, v.y, v.z, v.w};
#pragma unroll
            for (int j = 0; j < 4; j++) {
                int n = cc * 4 + j;
                __nv_bfloat16 h = __float2bfloat16(vv[j]);
                Bh[n * BSTRH + k] = h;
                Bl[n * BSTRH + k] = __float2bfloat16(vv[j] - __bfloat162float(h));
            }
        }
        __syncthreads();

        const unsigned* BhW = (const unsigned*)Bh;
        const unsigned* BlW = (const unsigned*)Bl;

#pragma unroll
        for (int ks = 0; ks < 4; ks++) {
            // prefetch next kstep's A (overlaps with convert+mma below)
            int knext = kt + ks * 16 + 16;
            if (knext < IN_DIM) {
#pragma unroll
                for (int i = 0; i < 4; i++) {
                    vn[2 * i]     = vld[i] ? __ldcs((const float2*)(xp[i] + knext + c0))
                                           : make_float2(0.f, 0.f);
                    vn[2 * i + 1] = vld[i] ? __ldcs((const float2*)(xp[i] + knext + c0 + 8))
                                           : make_float2(0.f, 0.f);
                }
            }
            // ---- in-register hi/lo split of current A fragments
            __nv_bfloat162 h2[8];
            unsigned ah[2][4], al[2][4];
            // tile0: rows lr, lr+8  (vc[0],vc[2] = k-lo; vc[1],vc[3] = k-hi)
            ah[0][0] = pack_hi(vc[0], &h2[0]);
            ah[0][1] = pack_hi(vc[2], &h2[2]);
            ah[0][2] = pack_hi(vc[1], &h2[1]);
            ah[0][3] = pack_hi(vc[3], &h2[3]);
            al[0][0] = pack_lo(vc[0], h2[0]);
            al[0][1] = pack_lo(vc[2], h2[2]);
            al[0][2] = pack_lo(vc[1], h2[1]);
            al[0][3] = pack_lo(vc[3], h2[3]);
            // tile1: rows lr+16, lr+24
            ah[1][0] = pack_hi(vc[4], &h2[4]);
            ah[1][1] = pack_hi(vc[6], &h2[6]);
            ah[1][2] = pack_hi(vc[5], &h2[5]);
            ah[1][3] = pack_hi(vc[7], &h2[7]);
            al[1][0] = pack_lo(vc[4], h2[4]);
            al[1][1] = pack_lo(vc[6], h2[6]);
            al[1][2] = pack_lo(vc[5], h2[5]);
            al[1][3] = pack_lo(vc[7], h2[7]);

#pragma unroll
            for (int nt = 0; nt < 8; nt++) {
                int nb = (nt * 8 + lr) * 36 + ks * 8 + q;
                unsigned bh[2] = {BhW[nb], BhW[nb + 4]};
                unsigned bl[2] = {BlW[nb], BlW[nb + 4]};
                mma16816(acc[0][nt], ah[0], bh);
                mma16816(acc[0][nt], ah[0], bl);
                mma16816(acc[0][nt], al[0], bh);
                mma16816(acc[1][nt], ah[1], bh);
                mma16816(acc[1][nt], ah[1], bl);
                mma16816(acc[1][nt], al[1], bh);
            }
#pragma unroll
            for (int i = 0; i < 8; i++) vc[i] = vn[i];
        }
    }

    // ---- epilogue
#pragma unroll
    for (int m = 0; m < 2; m++) {
        int r01 = rbase + m * 16 + lr;
        int r23 = r01 + 8;
        bool v01 = r01 < N_NODES, v23 = r23 < N_NODES;
#pragma unroll
        for (int nt = 0; nt < 8; nt++) {
            int col = nt * 8 + 2 * q;
            if (v01)
                *(float2*)&g_h1[(size_t)r01 * HID + col] =
                    make_float2(acc[m][nt][0], acc[m][nt][1]);
            if (v23)
                *(float2*)&g_h1[(size_t)r23 * HID + col] =
                    make_float2(acc[m][nt][2], acc[m][nt][3]);
        }
    }
}

// ---------------- agg1: out1 = A_norm @ h1 + b1, relu, then h2 = out1 @ W2 ----------------
__global__ __launch_bounds__(256) void k_agg1(const float* __restrict__ b1,
                                              const float* __restrict__ W2) {
    __shared__ float W2s[HID * OUTD];
    __shared__ float ha[8][HID];
    int tid = threadIdx.x;
    for (int i = tid; i < HID * OUTD; i += 256) W2s[i] = W2[i];
    __syncthreads();

    int w = tid >> 5, lane = tid & 31;
    int v = blockIdx.x * 8 + w;
    if (v >= N_NODES) return;

    const float2* __restrict__ H = (const float2*)g_h1;
    float dv = g_dinv[v];
    float ax = 0.f, ay = 0.f;

    {
        float2 p = H[(size_t)v * 32 + lane];
        float wgt = dv * dv;
        ax = fmaf(wgt, p.x, ax);
        ay = fmaf(wgt, p.y, ay);
    }
    int e = g_off[v], end = g_off[v + 1];
    for (; e + 4 <= end; e += 4) {
        int s0 = g_srcs[e], s1 = g_srcs[e + 1], s2 = g_srcs[e + 2], s3 = g_srcs[e + 3];
        float w0 = g_wgt[e], w1 = g_wgt[e + 1], w2 = g_wgt[e + 2], w3 = g_wgt[e + 3];
        float2 p0 = H[(size_t)s0 * 32 + lane];
        float2 p1 = H[(size_t)s1 * 32 + lane];
        float2 p2 = H[(size_t)s2 * 32 + lane];
        float2 p3 = H[(size_t)s3 * 32 + lane];
        ax = fmaf(w0, p0.x, ax); ay = fmaf(w0, p0.y, ay);
        ax = fmaf(w1, p1.x, ax); ay = fmaf(w1, p1.y, ay);
        ax = fmaf(w2, p2.x, ax); ay = fmaf(w2, p2.y, ay);
        ax = fmaf(w3, p3.x, ax); ay = fmaf(w3, p3.y, ay);
    }
    for (; e < end; ++e) {
        int s = g_srcs[e];
        float wg = g_wgt[e];
        float2 p = H[(size_t)s * 32 + lane];
        ax = fmaf(wg, p.x, ax);
        ay = fmaf(wg, p.y, ay);
    }
    ax = fmaxf(ax + b1[2 * lane], 0.f);
    ay = fmaxf(ay + b1[2 * lane + 1], 0.f);
    ha[w][2 * lane]     = ax;
    ha[w][2 * lane + 1] = ay;
    __syncwarp();

    float acc = 0.f;
#pragma unroll
    for (int k = 0; k < HID; k++) acc = fmaf(ha[w][k], W2s[k * OUTD + lane], acc);
    g_h2[(size_t)v * OUTD + lane] = acc;
}

// ---------------- agg2: out = A_norm @ h2 + b2, log_softmax ----------------
__global__ __launch_bounds__(256) void k_agg2(const float* __restrict__ b2,
                                              float* __restrict__ out) {
    int tid = threadIdx.x;
    int w = tid >> 5, lane = tid & 31;
    int v = blockIdx.x * 8 + w;
    if (v >= N_NODES) return;

    const float* __restrict__ H = g_h2;
    float dv = g_dinv[v];
    float a = dv * dv * H[(size_t)v * OUTD + lane];

    int e = g_off[v], end = g_off[v + 1];
    for (; e + 4 <= end; e += 4) {
        int s0 = g_srcs[e], s1 = g_srcs[e + 1], s2 = g_srcs[e + 2], s3 = g_srcs[e + 3];
        float w0 = g_wgt[e], w1 = g_wgt[e + 1], w2 = g_wgt[e + 2], w3 = g_wgt[e + 3];
        float p0 = H[(size_t)s0 * OUTD + lane];
        float p1 = H[(size_t)s1 * OUTD + lane];
        float p2 = H[(size_t)s2 * OUTD + lane];
        float p3 = H[(size_t)s3 * OUTD + lane];
        a = fmaf(w0, p0, a);
        a = fmaf(w1, p1, a);
        a = fmaf(w2, p2, a);
        a = fmaf(w3, p3, a);
    }
    for (; e < end; ++e) a = fmaf(g_wgt[e], H[(size_t)g_srcs[e] * OUTD + lane], a);
    a += b2[lane];

    float m = a;
#pragma unroll
    for (int o = 16; o > 0; o >>= 1) m = fmaxf(m, __shfl_xor_sync(0xffffffffu, m, o));
    float ex = expf(a - m);
    float ssum = ex;
#pragma unroll
    for (int o = 16; o > 0; o >>= 1) ssum += __shfl_xor_sync(0xffffffffu, ssum, o);
    out[(size_t)v * OUTD + lane] = a - m - logf(ssum);
}

// ---------------- launch ----------------
extern "C" void kernel_launch(void* const* d_in, const int* in_sizes, int n_in,
                              void* d_out, int out_size) {
    const float* x  = (const float*)d_in[0];
    const void*  ei = d_in[1];
    const float* W1 = (const float*)d_in[2];
    const float* b1 = (const float*)d_in[3];
    const float* W2 = (const float*)d_in[4];
    const float* b2 = (const float*)d_in[5];
    float* out = (float*)d_out;

    k_detect<<<1, 256>>>((const long long*)ei);
    k_init<<<(N_NODES + 255) / 256, 256>>>();
    k_hist<<<(N_EDGES + 255) / 256, 256>>>(ei);
    // position 4: the profiler samples the 4th launch
    k_gemm1<<<(N_NODES + BMG - 1) / BMG, 128>>>(x, W1);
    int nb = (N_NODES + 511) / 512;
    k_scan1<<<nb, 512>>>();
    k_scan2<<<1, 256>>>(nb);
    k_scan3<<<(N_NODES + 255) / 256, 256>>>();
    k_scatter<<<(N_EDGES + 255) / 256, 256>>>(ei);
    k_agg1<<<(N_NODES + 7) / 8, 256>>>(b1, W2);
    k_agg2<<<(N_NODES + 7) / 8, 256>>>(b2, out);
}

// round 5
// speedup vs baseline: 1.2058x; 1.2058x over previous
#include <cuda_runtime.h>
#include <cuda_bf16.h>
#include <math.h>

#define N_NODES 100000
#define N_EDGES 1600000
#define IN_DIM  512
#define HID     64
#define OUTD    32

// ---------------- scratch (static device globals; no allocation) ----------------
__device__ int   g_deg[N_NODES];
__device__ float g_dinv[N_NODES];
__device__ int   g_off[N_NODES + 1];
__device__ int   g_cur[N_NODES];
__device__ int   g_srcs[N_EDGES];
__device__ float g_wgt[N_EDGES];
__device__ float g_h1[(size_t)N_NODES * HID];   // 25.6 MB
__device__ float g_h2[(size_t)N_NODES * OUTD];  // 12.8 MB
__device__ int   g_bsum[256];
__device__ int   g_is64;

#define BSTRH 72  // halves per B row (64 + 8 pad); 36 words, conflict-free
// W1 pre-split hi/lo, laid out per 64-k chunk in the smem fragment layout
__device__ __nv_bfloat16 g_w1h[8][64][BSTRH];
__device__ __nv_bfloat16 g_w1l[8][64][BSTRH];

// ---------------- edge-index dtype detection (int64 vs int32) ----------------
__global__ void k_detect(const long long* __restrict__ ei) {
    __shared__ int ok;
    if (threadIdx.x == 0) ok = 1;
    __syncthreads();
    for (int j = threadIdx.x; j < 2048; j += blockDim.x) {
        long long v = ei[j];
        if (v < 0 || v >= N_NODES) atomicExch(&ok, 0);
    }
    __syncthreads();
    if (threadIdx.x == 0) g_is64 = ok;
}

__device__ __forceinline__ int load_edge(const void* ei, int part, int e) {
    if (g_is64) return (int)((const long long*)ei)[(size_t)part * N_EDGES + e];
    return ((const int*)ei)[(size_t)part * N_EDGES + e];
}

// ---------------- init: degree=1 (self loop) + one-time W1 hi/lo split ----------------
__global__ void k_init(const float* __restrict__ W1) {
    int v = blockIdx.x * blockDim.x + threadIdx.x;
    if (v < N_NODES) g_deg[v] = 1;
    if (v < IN_DIM * HID) {
        int k = v >> 6, n = v & 63;
        float w = W1[v];
        unsigned b = __float_as_uint(w);
        float hf = __uint_as_float(b & 0xFFFF0000u);
        float lf = w - hf;  // exact
        unsigned lb = __float_as_uint(lf);
        g_w1h[k >> 6][n][k & 63] = __ushort_as_bfloat16((unsigned short)(b >> 16));
        g_w1l[k >> 6][n][k & 63] = __ushort_as_bfloat16((unsigned short)(lb >> 16));
    }
}

__global__ void k_hist(const void* __restrict__ ei) {
    int e = blockIdx.x * blockDim.x + threadIdx.x;
    if (e < N_EDGES) atomicAdd(&g_deg[load_edge(ei, 1, e)], 1);
}

// ---------------- GEMM1: h1 = x @ W1, bf16 mma, truncate-split, no F2FP ----------------
#define BMG 128

__device__ __forceinline__ void mma16816(float* c, const unsigned* a, const unsigned* b) {
    asm volatile(
        "mma.sync.aligned.m16n8k16.row.col.f32.bf16.bf16.f32 "
        "{%0,%1,%2,%3}, {%4,%5,%6,%7}, {%8,%9}, {%0,%1,%2,%3};\n"
        : "+f"(c[0]), "+f"(c[1]), "+f"(c[2]), "+f"(c[3])
        : "r"(a[0]), "r"(a[1]), "r"(a[2]), "r"(a[3]), "r"(b[0]), "r"(b[1]));
}

__device__ __forceinline__ unsigned hi_pack(float2 v) {
    return __byte_perm(__float_as_uint(v.x), __float_as_uint(v.y), 0x7632);
}
__device__ __forceinline__ unsigned lo_pack(float2 v) {
    unsigned bx = __float_as_uint(v.x), by = __float_as_uint(v.y);
    float lx = v.x - __uint_as_float(bx & 0xFFFF0000u);
    float ly = v.y - __uint_as_float(by & 0xFFFF0000u);
    return __byte_perm(__float_as_uint(lx), __float_as_uint(ly), 0x7632);
}

__global__ __launch_bounds__(128, 4) void k_gemm1(const float* __restrict__ x,
                                                  const float* __restrict__ W1) {
    __shared__ __nv_bfloat16 Bh[64 * BSTRH];
    __shared__ __nv_bfloat16 Bl[64 * BSTRH];

    const int t = threadIdx.x;
    const int warp = t >> 5, lane = t & 31;
    const int q = lane & 3, lr = lane >> 2;
    const int rbase = blockIdx.x * BMG + warp * 32;

    bool vld[4];
    const float* xp[4];
#pragma unroll
    for (int i = 0; i < 4; i++) {
        int r = rbase + lr + i * 8;
        vld[i] = r < N_NODES;
        xp[i] = x + (size_t)(vld[i] ? r : 0) * IN_DIM;
    }

    float acc[2][8][4];
#pragma unroll
    for (int m = 0; m < 2; m++)
#pragma unroll
        for (int n = 0; n < 8; n++)
#pragma unroll
            for (int j = 0; j < 4; j++) acc[m][n][j] = 0.f;

    float2 vc[8], vn[8];
    const int c0 = 2 * q;

#pragma unroll
    for (int i = 0; i < 4; i++) {
        vc[2 * i]     = vld[i] ? __ldcs((const float2*)(xp[i] + c0))     : make_float2(0.f, 0.f);
        vc[2 * i + 1] = vld[i] ? __ldcs((const float2*)(xp[i] + c0 + 8)) : make_float2(0.f, 0.f);
    }

    for (int kt = 0; kt < IN_DIM; kt += 64) {
        __syncthreads();  // previous chunk's mma reads done
        // ---- copy pre-split W1 chunk into smem (pure memcpy, no math)
        {
            const int4* sh = (const int4*)g_w1h[kt >> 6];
            const int4* sl = (const int4*)g_w1l[kt >> 6];
            int4* dh = (int4*)Bh;
            int4* dl = (int4*)Bl;
            const int NW = 64 * BSTRH * 2 / 16;  // 576 int4
#pragma unroll
            for (int i = 0; i < 5; i++) {
                int idx = t + 128 * i;
                if (idx < NW) {
                    dh[idx] = sh[idx];
                    dl[idx] = sl[idx];
                }
            }
        }
        __syncthreads();

        const unsigned* BhW = (const unsigned*)Bh;
        const unsigned* BlW = (const unsigned*)Bl;

#pragma unroll
        for (int ks = 0; ks < 4; ks++) {
            int knext = kt + ks * 16 + 16;
            if (knext < IN_DIM) {
#pragma unroll
                for (int i = 0; i < 4; i++) {
                    vn[2 * i]     = vld[i] ? __ldcs((const float2*)(xp[i] + knext + c0))
                                           : make_float2(0.f, 0.f);
                    vn[2 * i + 1] = vld[i] ? __ldcs((const float2*)(xp[i] + knext + c0 + 8))
                                           : make_float2(0.f, 0.f);
                }
            }
            // ---- in-register truncate hi/lo split (PRMT/LOP3/FSUB only)
            unsigned ah[2][4], al[2][4];
            ah[0][0] = hi_pack(vc[0]); ah[0][1] = hi_pack(vc[2]);
            ah[0][2] = hi_pack(vc[1]); ah[0][3] = hi_pack(vc[3]);
            al[0][0] = lo_pack(vc[0]); al[0][1] = lo_pack(vc[2]);
            al[0][2] = lo_pack(vc[1]); al[0][3] = lo_pack(vc[3]);
            ah[1][0] = hi_pack(vc[4]); ah[1][1] = hi_pack(vc[6]);
            ah[1][2] = hi_pack(vc[5]); ah[1][3] = hi_pack(vc[7]);
            al[1][0] = lo_pack(vc[4]); al[1][1] = lo_pack(vc[6]);
            al[1][2] = lo_pack(vc[5]); al[1][3] = lo_pack(vc[7]);

#pragma unroll
            for (int nt = 0; nt < 8; nt++) {
                int nb = (nt * 8 + lr) * 36 + ks * 8 + q;
                unsigned bh[2] = {BhW[nb], BhW[nb + 4]};
                unsigned bl[2] = {BlW[nb], BlW[nb + 4]};
                mma16816(acc[0][nt], ah[0], bh);
                mma16816(acc[0][nt], ah[0], bl);
                mma16816(acc[0][nt], al[0], bh);
                mma16816(acc[1][nt], ah[1], bh);
                mma16816(acc[1][nt], ah[1], bl);
                mma16816(acc[1][nt], al[1], bh);
            }
#pragma unroll
            for (int i = 0; i < 8; i++) vc[i] = vn[i];
        }
    }

#pragma unroll
    for (int m = 0; m < 2; m++) {
        int r01 = rbase + m * 16 + lr;
        int r23 = r01 + 8;
        bool v01 = r01 < N_NODES, v23 = r23 < N_NODES;
#pragma unroll
        for (int nt = 0; nt < 8; nt++) {
            int col = nt * 8 + 2 * q;
            if (v01)
                *(float2*)&g_h1[(size_t)r01 * HID + col] =
                    make_float2(acc[m][nt][0], acc[m][nt][1]);
            if (v23)
                *(float2*)&g_h1[(size_t)r23 * HID + col] =
                    make_float2(acc[m][nt][2], acc[m][nt][3]);
        }
    }
}

// ---------------- exclusive scan of (deg-1) to build CSR offsets ----------------
__global__ void k_scan1() {
    __shared__ int s[512];
    int t = threadIdx.x;
    int v = blockIdx.x * 512 + t;
    int c = (v < N_NODES) ? (g_deg[v] - 1) : 0;
    s[t] = c;
    __syncthreads();
    for (int o = 1; o < 512; o <<= 1) {
        int val = (t >= o) ? s[t - o] : 0;
        __syncthreads();
        s[t] += val;
        __syncthreads();
    }
    if (v < N_NODES) g_off[v] = s[t] - c;
    if (t == 511) g_bsum[blockIdx.x] = s[511];
}

__global__ void k_scan2(int nb) {
    __shared__ int s[256];
    int t = threadIdx.x;
    int c = (t < nb) ? g_bsum[t] : 0;
    s[t] = c;
    __syncthreads();
    for (int o = 1; o < 256; o <<= 1) {
        int val = (t >= o) ? s[t - o] : 0;
        __syncthreads();
        s[t] += val;
        __syncthreads();
    }
    if (t < nb) g_bsum[t] = s[t] - c;
}

__global__ void k_scan3() {  // finalize offsets + compute dinv
    int v = blockIdx.x * blockDim.x + threadIdx.x;
    if (v < N_NODES) {
        int o = g_off[v] + g_bsum[v >> 9];
        g_off[v] = o;
        g_cur[v] = o;
        g_dinv[v] = rsqrtf((float)g_deg[v]);
    }
    if (v == 0) g_off[N_NODES] = N_EDGES;
}

__global__ void k_scatter(const void* __restrict__ ei) {
    int e = blockIdx.x * blockDim.x + threadIdx.x;
    if (e < N_EDGES) {
        int d = load_edge(ei, 1, e);
        int s = load_edge(ei, 0, e);
        int pos = atomicAdd(&g_cur[d], 1);
        g_srcs[pos] = s;
        g_wgt[pos] = g_dinv[s] * g_dinv[d];
    }
}

// ---------------- agg1: out1 = A_norm @ h1 + b1, relu, then h2 = out1 @ W2 ----------------
__global__ __launch_bounds__(256) void k_agg1(const float* __restrict__ b1,
                                              const float* __restrict__ W2) {
    __shared__ float W2s[HID * OUTD];
    __shared__ float ha[8][HID];
    int tid = threadIdx.x;
    for (int i = tid; i < HID * OUTD; i += 256) W2s[i] = W2[i];
    __syncthreads();

    int w = tid >> 5, lane = tid & 31;
    int v = blockIdx.x * 8 + w;
    if (v >= N_NODES) return;

    const float2* __restrict__ H = (const float2*)g_h1;
    float dv = g_dinv[v];
    float ax = 0.f, ay = 0.f;

    {
        float2 p = H[(size_t)v * 32 + lane];
        float wgt = dv * dv;
        ax = fmaf(wgt, p.x, ax);
        ay = fmaf(wgt, p.y, ay);
    }
    int e = g_off[v], end = g_off[v + 1];
    for (; e + 4 <= end; e += 4) {
        int s0 = g_srcs[e], s1 = g_srcs[e + 1], s2 = g_srcs[e + 2], s3 = g_srcs[e + 3];
        float w0 = g_wgt[e], w1 = g_wgt[e + 1], w2 = g_wgt[e + 2], w3 = g_wgt[e + 3];
        float2 p0 = H[(size_t)s0 * 32 + lane];
        float2 p1 = H[(size_t)s1 * 32 + lane];
        float2 p2 = H[(size_t)s2 * 32 + lane];
        float2 p3 = H[(size_t)s3 * 32 + lane];
        ax = fmaf(w0, p0.x, ax); ay = fmaf(w0, p0.y, ay);
        ax = fmaf(w1, p1.x, ax); ay = fmaf(w1, p1.y, ay);
        ax = fmaf(w2, p2.x, ax); ay = fmaf(w2, p2.y, ay);
        ax = fmaf(w3, p3.x, ax); ay = fmaf(w3, p3.y, ay);
    }
    for (; e < end; ++e) {
        int s = g_srcs[e];
        float wg = g_wgt[e];
        float2 p = H[(size_t)s * 32 + lane];
        ax = fmaf(wg, p.x, ax);
        ay = fmaf(wg, p.y, ay);
    }
    ax = fmaxf(ax + b1[2 * lane], 0.f);
    ay = fmaxf(ay + b1[2 * lane + 1], 0.f);
    ha[w][2 * lane]     = ax;
    ha[w][2 * lane + 1] = ay;
    __syncwarp();

    float acc = 0.f;
#pragma unroll
    for (int k = 0; k < HID; k++) acc = fmaf(ha[w][k], W2s[k * OUTD + lane], acc);
    g_h2[(size_t)v * OUTD + lane] = acc;
}

// ---------------- agg2: out = A_norm @ h2 + b2, log_softmax ----------------
__global__ __launch_bounds__(256) void k_agg2(const float* __restrict__ b2,
                                              float* __restrict__ out) {
    int tid = threadIdx.x;
    int w = tid >> 5, lane = tid & 31;
    int v = blockIdx.x * 8 + w;
    if (v >= N_NODES) return;

    const float* __restrict__ H = g_h2;
    float dv = g_dinv[v];
    float a = dv * dv * H[(size_t)v * OUTD + lane];

    int e = g_off[v], end = g_off[v + 1];
    for (; e + 4 <= end; e += 4) {
        int s0 = g_srcs[e], s1 = g_srcs[e + 1], s2 = g_srcs[e + 2], s3 = g_srcs[e + 3];
        float w0 = g_wgt[e], w1 = g_wgt[e + 1], w2 = g_wgt[e + 2], w3 = g_wgt[e + 3];
        float p0 = H[(size_t)s0 * OUTD + lane];
        float p1 = H[(size_t)s1 * OUTD + lane];
        float p2 = H[(size_t)s2 * OUTD + lane];
        float p3 = H[(size_t)s3 * OUTD + lane];
        a = fmaf(w0, p0, a);
        a = fmaf(w1, p1, a);
        a = fmaf(w2, p2, a);
        a = fmaf(w3, p3, a);
    }
    for (; e < end; ++e) a = fmaf(g_wgt[e], H[(size_t)g_srcs[e] * OUTD + lane], a);
    a += b2[lane];

    float m = a;
#pragma unroll
    for (int o = 16; o > 0; o >>= 1) m = fmaxf(m, __shfl_xor_sync(0xffffffffu, m, o));
    float ex = expf(a - m);
    float ssum = ex;
#pragma unroll
    for (int o = 16; o > 0; o >>= 1) ssum += __shfl_xor_sync(0xffffffffu, ssum, o);
    out[(size_t)v * OUTD + lane] = a - m - logf(ssum);
}

// ---------------- launch ----------------
extern "C" void kernel_launch(void* const* d_in, const int* in_sizes, int n_in,
                              void* d_out, int out_size) {
    const float* x  = (const float*)d_in[0];
    const void*  ei = d_in[1];
    const float* W1 = (const float*)d_in[2];
    const float* b1 = (const float*)d_in[3];
    const float* W2 = (const float*)d_in[4];
    const float* b2 = (const float*)d_in[5];
    float* out = (float*)d_out;

    k_detect<<<1, 256>>>((const long long*)ei);
    k_init<<<(N_NODES + 255) / 256, 256>>>(W1);  // also pre-splits W1
    k_hist<<<(N_EDGES + 255) / 256, 256>>>(ei);
    // position 4: the profiler samples the 4th launch
    k_gemm1<<<(N_NODES + BMG - 1) / BMG, 128>>>(x, W1);
    int nb = (N_NODES + 511) / 512;
    k_scan1<<<nb, 512>>>();
    k_scan2<<<1, 256>>>(nb);
    k_scan3<<<(N_NODES + 255) / 256, 256>>>();
    k_scatter<<<(N_EDGES + 255) / 256, 256>>>(ei);
    k_agg1<<<(N_NODES + 7) / 8, 256>>>(b1, W2);
    k_agg2<<<(N_NODES + 7) / 8, 256>>>(b2, out);
}

// round 6
// speedup vs baseline: 1.2261x; 1.0169x over previous
#include <cuda_runtime.h>
#include <cuda_bf16.h>
#include <math.h>

#define N_NODES 100000
#define N_EDGES 1600000
#define IN_DIM  512
#define HID     64
#define OUTD    32

// ---------------- scratch (static device globals; no allocation) ----------------
__device__ int   g_deg[N_NODES];
__device__ float g_dinv[N_NODES];
__device__ int   g_off[N_NODES + 1];
__device__ int   g_cur[N_NODES];
__device__ int   g_srcs[N_EDGES];
__device__ float g_wgt[N_EDGES];
__device__ float g_h1[(size_t)N_NODES * HID];   // 25.6 MB
__device__ float g_h2[(size_t)N_NODES * OUTD];  // 12.8 MB
__device__ int   g_bsum[256];
__device__ int   g_is64;

// W1 pre-packed into per-lane mma fragments:
// [chunk][ (ks*8+nt)*32 + lane ] = {bh0, bh1, bl0, bl1}
__device__ uint4 g_w1p[8][1024];   // 128 KB

// ---------------- edge-index dtype detection (int64 vs int32) ----------------
__global__ void k_detect(const long long* __restrict__ ei) {
    __shared__ int ok;
    if (threadIdx.x == 0) ok = 1;
    __syncthreads();
    for (int j = threadIdx.x; j < 2048; j += blockDim.x) {
        long long v = ei[j];
        if (v < 0 || v >= N_NODES) atomicExch(&ok, 0);
    }
    __syncthreads();
    if (threadIdx.x == 0) g_is64 = ok;
}

__device__ __forceinline__ int load_edge(const void* ei, int part, int e) {
    if (g_is64) return (int)((const long long*)ei)[(size_t)part * N_EDGES + e];
    return ((const int*)ei)[(size_t)part * N_EDGES + e];
}

__device__ __forceinline__ unsigned hi16(float f) {
    return __float_as_uint(f) >> 16;
}
__device__ __forceinline__ unsigned lo16(float f) {
    float hf = __uint_as_float(__float_as_uint(f) & 0xFFFF0000u);
    return __float_as_uint(f - hf) >> 16;
}

// ---------------- init: degree=1 + one-time W1 fragment pre-pack ----------------
__global__ void k_init(const float* __restrict__ W1) {
    int v = blockIdx.x * blockDim.x + threadIdx.x;
    if (v < N_NODES) g_deg[v] = 1;
    if (v < 8192) {
        int lane = v & 31, nt = (v >> 5) & 7, ks = (v >> 8) & 3, chunk = v >> 10;
        int q = lane & 3, lr = lane >> 2;
        int n = nt * 8 + lr;
        int k0 = chunk * 64 + ks * 16 + 2 * q;
        float w00 = W1[(size_t)k0 * 64 + n];
        float w01 = W1[(size_t)(k0 + 1) * 64 + n];
        float w10 = W1[(size_t)(k0 + 8) * 64 + n];
        float w11 = W1[(size_t)(k0 + 9) * 64 + n];
        uint4 f;
        f.x = hi16(w00) | (hi16(w01) << 16);
        f.y = hi16(w10) | (hi16(w11) << 16);
        f.z = lo16(w00) | (lo16(w01) << 16);
        f.w = lo16(w10) | (lo16(w11) << 16);
        g_w1p[chunk][(ks * 8 + nt) * 32 + lane] = f;
    }
}

__global__ void k_hist(const void* __restrict__ ei) {
    int e = blockIdx.x * blockDim.x + threadIdx.x;
    if (e < N_EDGES) atomicAdd(&g_deg[load_edge(ei, 1, e)], 1);
}

// ---------------- GEMM1: h1 = x @ W1, bf16 mma, fragment-packed B ----------------
#define BMG 128

__device__ __forceinline__ void mma16816(float* c, const unsigned* a, const unsigned* b) {
    asm volatile(
        "mma.sync.aligned.m16n8k16.row.col.f32.bf16.bf16.f32 "
        "{%0,%1,%2,%3}, {%4,%5,%6,%7}, {%8,%9}, {%0,%1,%2,%3};\n"
        : "+f"(c[0]), "+f"(c[1]), "+f"(c[2]), "+f"(c[3])
        : "r"(a[0]), "r"(a[1]), "r"(a[2]), "r"(a[3]), "r"(b[0]), "r"(b[1]));
}

__device__ __forceinline__ unsigned hi_pack(float2 v) {
    return __byte_perm(__float_as_uint(v.x), __float_as_uint(v.y), 0x7632);
}
__device__ __forceinline__ unsigned lo_pack(float2 v) {
    unsigned bx = __float_as_uint(v.x), by = __float_as_uint(v.y);
    float lx = v.x - __uint_as_float(bx & 0xFFFF0000u);
    float ly = v.y - __uint_as_float(by & 0xFFFF0000u);
    return __byte_perm(__float_as_uint(lx), __float_as_uint(ly), 0x7632);
}

__global__ __launch_bounds__(128, 4) void k_gemm1(const float* __restrict__ x) {
    __shared__ uint4 Bp[1024];  // 16 KB fragment-packed W1 chunk

    const int t = threadIdx.x;
    const int warp = t >> 5, lane = t & 31;
    const int q = lane & 3, lr = lane >> 2;
    const int rbase = blockIdx.x * BMG + warp * 32;

    bool vld[4];
    const float* xp[4];
#pragma unroll
    for (int i = 0; i < 4; i++) {
        int r = rbase + lr + i * 8;
        vld[i] = r < N_NODES;
        xp[i] = x + (size_t)(vld[i] ? r : 0) * IN_DIM;
    }

    float acc[2][8][4];
#pragma unroll
    for (int m = 0; m < 2; m++)
#pragma unroll
        for (int n = 0; n < 8; n++)
#pragma unroll
            for (int j = 0; j < 4; j++) acc[m][n][j] = 0.f;

    float2 vc[8], vn[8];
    const int c0 = 2 * q;

#pragma unroll
    for (int i = 0; i < 4; i++) {
        vc[2 * i]     = vld[i] ? __ldcs((const float2*)(xp[i] + c0))     : make_float2(0.f, 0.f);
        vc[2 * i + 1] = vld[i] ? __ldcs((const float2*)(xp[i] + c0 + 8)) : make_float2(0.f, 0.f);
    }

    for (int kt = 0; kt < IN_DIM; kt += 64) {
        __syncthreads();  // previous chunk's fragment reads done
        {
            const uint4* src = g_w1p[kt >> 6];
#pragma unroll
            for (int i = 0; i < 8; i++) Bp[t + 128 * i] = src[t + 128 * i];
        }
        __syncthreads();

#pragma unroll
        for (int ks = 0; ks < 4; ks++) {
            int knext = kt + ks * 16 + 16;
            if (knext < IN_DIM) {
#pragma unroll
                for (int i = 0; i < 4; i++) {
                    vn[2 * i]     = vld[i] ? __ldcs((const float2*)(xp[i] + knext + c0))
                                           : make_float2(0.f, 0.f);
                    vn[2 * i + 1] = vld[i] ? __ldcs((const float2*)(xp[i] + knext + c0 + 8))
                                           : make_float2(0.f, 0.f);
                }
            }
            // in-register truncate hi/lo split of A
            unsigned ah[2][4], al[2][4];
            ah[0][0] = hi_pack(vc[0]); ah[0][1] = hi_pack(vc[2]);
            ah[0][2] = hi_pack(vc[1]); ah[0][3] = hi_pack(vc[3]);
            al[0][0] = lo_pack(vc[0]); al[0][1] = lo_pack(vc[2]);
            al[0][2] = lo_pack(vc[1]); al[0][3] = lo_pack(vc[3]);
            ah[1][0] = hi_pack(vc[4]); ah[1][1] = hi_pack(vc[6]);
            ah[1][2] = hi_pack(vc[5]); ah[1][3] = hi_pack(vc[7]);
            al[1][0] = lo_pack(vc[4]); al[1][1] = lo_pack(vc[6]);
            al[1][2] = lo_pack(vc[5]); al[1][3] = lo_pack(vc[7]);

#pragma unroll
            for (int nt = 0; nt < 8; nt++) {
                uint4 f = Bp[(ks * 8 + nt) * 32 + lane];  // one LDS.128
                unsigned bh[2] = {f.x, f.y};
                unsigned bl[2] = {f.z, f.w};
                mma16816(acc[0][nt], ah[0], bh);
                mma16816(acc[0][nt], ah[0], bl);
                mma16816(acc[0][nt], al[0], bh);
                mma16816(acc[1][nt], ah[1], bh);
                mma16816(acc[1][nt], ah[1], bl);
                mma16816(acc[1][nt], al[1], bh);
            }
#pragma unroll
            for (int i = 0; i < 8; i++) vc[i] = vn[i];
        }
    }

#pragma unroll
    for (int m = 0; m < 2; m++) {
        int r01 = rbase + m * 16 + lr;
        int r23 = r01 + 8;
        bool v01 = r01 < N_NODES, v23 = r23 < N_NODES;
#pragma unroll
        for (int nt = 0; nt < 8; nt++) {
            int col = nt * 8 + 2 * q;
            if (v01)
                *(float2*)&g_h1[(size_t)r01 * HID + col] =
                    make_float2(acc[m][nt][0], acc[m][nt][1]);
            if (v23)
                *(float2*)&g_h1[(size_t)r23 * HID + col] =
                    make_float2(acc[m][nt][2], acc[m][nt][3]);
        }
    }
}

// ---------------- exclusive scan of (deg-1) to build CSR offsets ----------------
__global__ void k_scan1() {
    __shared__ int s[512];
    int t = threadIdx.x;
    int v = blockIdx.x * 512 + t;
    int c = (v < N_NODES) ? (g_deg[v] - 1) : 0;
    s[t] = c;
    __syncthreads();
    for (int o = 1; o < 512; o <<= 1) {
        int val = (t >= o) ? s[t - o] : 0;
        __syncthreads();
        s[t] += val;
        __syncthreads();
    }
    if (v < N_NODES) g_off[v] = s[t] - c;
    if (t == 511) g_bsum[blockIdx.x] = s[511];
}

__global__ void k_scan2(int nb) {
    __shared__ int s[256];
    int t = threadIdx.x;
    int c = (t < nb) ? g_bsum[t] : 0;
    s[t] = c;
    __syncthreads();
    for (int o = 1; o < 256; o <<= 1) {
        int val = (t >= o) ? s[t - o] : 0;
        __syncthreads();
        s[t] += val;
        __syncthreads();
    }
    if (t < nb) g_bsum[t] = s[t] - c;
}

__global__ void k_scan3() {
    int v = blockIdx.x * blockDim.x + threadIdx.x;
    if (v < N_NODES) {
        int o = g_off[v] + g_bsum[v >> 9];
        g_off[v] = o;
        g_cur[v] = o;
        g_dinv[v] = rsqrtf((float)g_deg[v]);
    }
    if (v == 0) g_off[N_NODES] = N_EDGES;
}

__global__ void k_scatter(const void* __restrict__ ei) {
    int e = blockIdx.x * blockDim.x + threadIdx.x;
    if (e < N_EDGES) {
        int d = load_edge(ei, 1, e);
        int s = load_edge(ei, 0, e);
        int pos = atomicAdd(&g_cur[d], 1);
        g_srcs[pos] = s;
        g_wgt[pos] = g_dinv[s] * g_dinv[d];
    }
}

// ---------------- agg1: half-warp float4 gather + fused layer-2 GEMM ----------------
__global__ __launch_bounds__(256) void k_agg1(const float* __restrict__ b1,
                                              const float* __restrict__ W2) {
    __shared__ float W2s[HID * OUTD];
    __shared__ float ha[8][HID];
    int tid = threadIdx.x;
    for (int i = tid; i < HID * OUTD; i += 256) W2s[i] = W2[i];
    __syncthreads();

    int w = tid >> 5, lane = tid & 31;
    int v = blockIdx.x * 8 + w;
    if (v >= N_NODES) return;

    int half = lane >> 4, hl = lane & 15;
    const float4* __restrict__ H = (const float4*)g_h1;  // 16 float4 per row
    float dv = g_dinv[v];
    float ax = 0.f, ay = 0.f, az = 0.f, aw = 0.f;

    if (!half) {  // self loop once
        float4 p = H[(size_t)v * 16 + hl];
        float wg = dv * dv;
        ax = wg * p.x; ay = wg * p.y; az = wg * p.z; aw = wg * p.w;
    }
    int e = g_off[v] + half, end = g_off[v + 1];
    for (; e + 4 < end; e += 6) {  // 3 edges per parity stream in flight
        int s0 = g_srcs[e], s1 = g_srcs[e + 2], s2 = g_srcs[e + 4];
        float w0 = g_wgt[e], w1 = g_wgt[e + 2], w2 = g_wgt[e + 4];
        float4 p0 = H[(size_t)s0 * 16 + hl];
        float4 p1 = H[(size_t)s1 * 16 + hl];
        float4 p2 = H[(size_t)s2 * 16 + hl];
        ax = fmaf(w0, p0.x, ax); ay = fmaf(w0, p0.y, ay);
        az = fmaf(w0, p0.z, az); aw = fmaf(w0, p0.w, aw);
        ax = fmaf(w1, p1.x, ax); ay = fmaf(w1, p1.y, ay);
        az = fmaf(w1, p1.z, az); aw = fmaf(w1, p1.w, aw);
        ax = fmaf(w2, p2.x, ax); ay = fmaf(w2, p2.y, ay);
        az = fmaf(w2, p2.z, az); aw = fmaf(w2, p2.w, aw);
    }
    for (; e < end; e += 2) {
        int s = g_srcs[e];
        float wg = g_wgt[e];
        float4 p = H[(size_t)s * 16 + hl];
        ax = fmaf(wg, p.x, ax); ay = fmaf(wg, p.y, ay);
        az = fmaf(wg, p.z, az); aw = fmaf(wg, p.w, aw);
    }
    // combine parity halves
    ax += __shfl_xor_sync(0xffffffffu, ax, 16);
    ay += __shfl_xor_sync(0xffffffffu, ay, 16);
    az += __shfl_xor_sync(0xffffffffu, az, 16);
    aw += __shfl_xor_sync(0xffffffffu, aw, 16);

    if (!half) {
        float4 bb = *(const float4*)(b1 + hl * 4);
        float4 r;
        r.x = fmaxf(ax + bb.x, 0.f);
        r.y = fmaxf(ay + bb.y, 0.f);
        r.z = fmaxf(az + bb.z, 0.f);
        r.w = fmaxf(aw + bb.w, 0.f);
        *(float4*)&ha[w][hl * 4] = r;
    }
    __syncwarp();

    float acc = 0.f;
#pragma unroll
    for (int k = 0; k < HID; k++) acc = fmaf(ha[w][k], W2s[k * OUTD + lane], acc);
    g_h2[(size_t)v * OUTD + lane] = acc;
}

// ---------------- agg2: half-warp float2 gather + log_softmax ----------------
__global__ __launch_bounds__(256) void k_agg2(const float* __restrict__ b2,
                                              float* __restrict__ out) {
    int tid = threadIdx.x;
    int w = tid >> 5, lane = tid & 31;
    int v = blockIdx.x * 8 + w;
    if (v >= N_NODES) return;

    int half = lane >> 4, hl = lane & 15;
    const float2* __restrict__ H = (const float2*)g_h2;  // 16 float2 per row
    float dv = g_dinv[v];
    float ax = 0.f, ay = 0.f;

    if (!half) {
        float2 p = H[(size_t)v * 16 + hl];
        float wg = dv * dv;
        ax = wg * p.x; ay = wg * p.y;
    }
    int e = g_off[v] + half, end = g_off[v + 1];
    for (; e + 4 < end; e += 6) {
        int s0 = g_srcs[e], s1 = g_srcs[e + 2], s2 = g_srcs[e + 4];
        float w0 = g_wgt[e], w1 = g_wgt[e + 2], w2 = g_wgt[e + 4];
        float2 p0 = H[(size_t)s0 * 16 + hl];
        float2 p1 = H[(size_t)s1 * 16 + hl];
        float2 p2 = H[(size_t)s2 * 16 + hl];
        ax = fmaf(w0, p0.x, ax); ay = fmaf(w0, p0.y, ay);
        ax = fmaf(w1, p1.x, ax); ay = fmaf(w1, p1.y, ay);
        ax = fmaf(w2, p2.x, ax); ay = fmaf(w2, p2.y, ay);
    }
    for (; e < end; e += 2) {
        int s = g_srcs[e];
        float wg = g_wgt[e];
        float2 p = H[(size_t)s * 16 + hl];
        ax = fmaf(wg, p.x, ax); ay = fmaf(wg, p.y, ay);
    }
    ax += __shfl_xor_sync(0xffffffffu, ax, 16);
    ay += __shfl_xor_sync(0xffffffffu, ay, 16);

    ax += b2[2 * hl];
    ay += b2[2 * hl + 1];

    float m = fmaxf(ax, ay);
#pragma unroll
    for (int o = 1; o < 16; o <<= 1) m = fmaxf(m, __shfl_xor_sync(0xffffffffu, m, o));
    float ex = expf(ax - m) + expf(ay - m);
#pragma unroll
    for (int o = 1; o < 16; o <<= 1) ex += __shfl_xor_sync(0xffffffffu, ex, o);
    float ls = logf(ex);
    if (!half)
        *(float2*)&out[(size_t)v * OUTD + 2 * hl] = make_float2(ax - m - ls, ay - m - ls);
}

// ---------------- launch ----------------
extern "C" void kernel_launch(void* const* d_in, const int* in_sizes, int n_in,
                              void* d_out, int out_size) {
    const float* x  = (const float*)d_in[0];
    const void*  ei = d_in[1];
    const float* W1 = (const float*)d_in[2];
    const float* b1 = (const float*)d_in[3];
    const float* W2 = (const float*)d_in[4];
    const float* b2 = (const float*)d_in[5];
    float* out = (float*)d_out;

    k_detect<<<1, 256>>>((const long long*)ei);
    k_init<<<(N_NODES + 255) / 256, 256>>>(W1);  // also pre-packs W1 fragments
    k_hist<<<(N_EDGES + 255) / 256, 256>>>(ei);
    // position 4: the profiler samples the 4th launch
    k_gemm1<<<(N_NODES + BMG - 1) / BMG, 128>>>(x);
    int nb = (N_NODES + 511) / 512;
    k_scan1<<<nb, 512>>>();
    k_scan2<<<1, 256>>>(nb);
    k_scan3<<<(N_NODES + 255) / 256, 256>>>();
    k_scatter<<<(N_EDGES + 255) / 256, 256>>>(ei);
    k_agg1<<<(N_NODES + 7) / 8, 256>>>(b1, W2);
    k_agg2<<<(N_NODES + 7) / 8, 256>>>(b2, out);
}